// round 15
// baseline (speedup 1.0000x reference)
#include <cuda_runtime.h>
#include <cuda_bf16.h>
#include <cstdint>

// SparseBoundaryContent: x [16, 512, 64] f32.
// boundary(i,j) = (x[i]+x[j])/2 on masked cells, content(i,j) = max(x[i..j])
// on masked cells, 0 elsewhere.
// Output layout (flat f32): [boundary B*D*N*N][content B*D*N*N][mask B*N*N].
//
// R14: R13 champion + two-phase store issue: scatter rows i<32, launch their
// 8KB bulk stores, then scatter rows i>=32 and launch the rest. Earlier TMA
// injection shortens the CTA critical path (matters only in ramp/tail waves;
// steady state is pinned at the chip-wide ~6300 B/cyc LTS store cap).

#define NB 16
#define ND 512
#define NN 64
#define NCELLS 4096          // 64*64 cells per (b,d) row
#define HCELLS 2048          // cells per half (rows i<32 / i>=32)
#define NMASKED 1104         // masked cells per tile (incl. diagonal)
#define SPLIT 676            // meta entries with i < 32

constexpr bool cell_mask_ct(int i, int j) {
    int d = j - i;
    if (d < 0)  return false;
    if (d <= 15) return true;                              // stride-1 offsets 0..15
    if (d <= 31) return (d & 1) && !(i & 1);               // stride-2: odd 17..31, i even
    return (d >= 35) && ((d & 3) == 3) && !(i & 3);        // stride-4: 35,39,..,63, i%4==0
}

struct MaskTab { float m[NCELLS]; };
constexpr MaskTab gen_mask() {
    MaskTab t{};
    for (int i = 0; i < NN; i++)
        for (int j = 0; j < NN; j++)
            t.m[i * NN + j] = cell_mask_ct(i, j) ? 1.0f : 0.0f;
    return t;
}
__device__ constexpr MaskTab g_mask = gen_mask();

struct Meta { unsigned int m[NMASKED]; };
constexpr Meta gen_meta() {
    Meta t{};
    int cnt = 0;
    for (int i = 0; i < NN; i++) {                         // i-major: i<32 first
        for (int j = 0; j < NN; j++) {
            if (!cell_mask_ct(i, j)) continue;
            int len = j - i + 1;
            int k = 0;
            while ((1 << (k + 1)) <= len) k++;             // floor(log2(len))
            int ri = j + 1 - (1 << k);
            unsigned offL = (unsigned)(k * NN + i);
            unsigned offR = (unsigned)(k * NN + ri);
            t.m[cnt++] = (unsigned)(i * NN + j) | (offL << 12) | (offR << 21);
        }
    }
    return t;
}
__device__ constexpr Meta g_meta = gen_meta();

constexpr int count_half0() {
    int c = 0;
    for (int i = 0; i < 32; i++)
        for (int j = 0; j < NN; j++)
            if (cell_mask_ct(i, j)) c++;
    return c;
}
static_assert(count_half0() == SPLIT, "half-0 split mismatch");

__device__ __forceinline__ uint32_t smem_u32(const void* p) {
    uint32_t a;
    asm("{ .reg .u64 t; cvta.to.shared.u64 t, %1; cvt.u32.u64 %0, t; }"
        : "=r"(a) : "l"(p));
    return a;
}

__global__ void __launch_bounds__(256)
sbc_kernel(const float* __restrict__ x,
           float* __restrict__ boundary,
           float* __restrict__ content,
           float* __restrict__ mask_out)
{
    __shared__ float Mf[7 * NN];                 // sparse max table
    __shared__ alignas(128) float bt[NCELLS];    // boundary tile (16 KB)
    __shared__ alignas(128) float ct[NCELLS];    // content tile  (16 KB)

    const int bd  = blockIdx.x;                  // bd = b*ND + d
    const int tid = threadIdx.x;
    const int wid = tid >> 5;
    const int lid = tid & 31;

    float* gb = boundary + (size_t)bd * NCELLS;
    float* gc = content  + (size_t)bd * NCELLS;

    // Warp 0: early x load + sparse-max build (syncwarp only) with its
    // zero-fill share covering the LDG latency. Warps 1..7: zero-fill tiles.
    if (wid == 0) {
        const float* xr = x + (size_t)bd * NN;
        const float x0 = xr[lid];
        const float x1 = xr[lid + 32];
        const float4 z = make_float4(0.f, 0.f, 0.f, 0.f);
        #pragma unroll
        for (int p = 0; p < 4; p++) {
            reinterpret_cast<float4*>(bt)[p * 256 + tid] = z;
            reinterpret_cast<float4*>(ct)[p * 256 + tid] = z;
        }
        Mf[lid]      = x0;
        Mf[lid + 32] = x1;
        __syncwarp();
        #pragma unroll
        for (int k = 1; k < 7; k++) {
            const int h  = 1 << (k - 1);
            const int e1 = lid + 32;
            int o0 = lid + h; if (o0 > 63) o0 = 63;
            int o1 = e1  + h; if (o1 > 63) o1 = 63;
            const float a = fmaxf(Mf[(k - 1) * NN + lid], Mf[(k - 1) * NN + o0]);
            const float b = fmaxf(Mf[(k - 1) * NN + e1],  Mf[(k - 1) * NN + o1]);
            Mf[k * NN + lid] = a;
            Mf[k * NN + e1]  = b;
            __syncwarp();
        }
    } else {
        const float4 z = make_float4(0.f, 0.f, 0.f, 0.f);
        #pragma unroll
        for (int p = 0; p < 4; p++) {
            reinterpret_cast<float4*>(bt)[p * 256 + tid] = z;
            reinterpret_cast<float4*>(ct)[p * 256 + tid] = z;
        }
    }
    __syncthreads();   // Mf ready, tiles zeroed

    // Phase 1: scatter rows i<32 (entries 0..675 -> cells 0..2047).
    #pragma unroll
    for (int p = 0; p < 3; p++) {
        const int idx = p * 256 + tid;
        if (idx < SPLIT) {
            const unsigned m    = g_meta.m[idx];
            const int      cell = m & 4095u;
            const int      i    = cell >> 6;
            const int      j    = cell & 63;
            bt[cell] = (Mf[i] + Mf[j]) * 0.5f;
            ct[cell] = fmaxf(Mf[(m >> 12) & 511u], Mf[(m >> 21) & 511u]);
        }
    }
    asm volatile("fence.proxy.async.shared::cta;" ::: "memory");
    __syncthreads();   // zero-fill + half-0 scatter visible to async proxy

    // Issue half-0 stores immediately (8 KB each, two independent groups).
    if (tid == 0) {
        asm volatile("cp.async.bulk.global.shared::cta.bulk_group [%0], [%1], %2;"
                     :: "l"(gb), "r"(smem_u32(bt)), "n"(HCELLS * 4) : "memory");
        asm volatile("cp.async.bulk.commit_group;" ::: "memory");
    } else if (tid == 128) {
        asm volatile("cp.async.bulk.global.shared::cta.bulk_group [%0], [%1], %2;"
                     :: "l"(gc), "r"(smem_u32(ct)), "n"(HCELLS * 4) : "memory");
        asm volatile("cp.async.bulk.commit_group;" ::: "memory");
    }

    // Phase 2: scatter rows i>=32 (entries 676..1103 -> cells 2048..4095).
    // Disjoint from the smem ranges the in-flight TMA reads.
    #pragma unroll
    for (int p = 0; p < 2; p++) {
        const int idx = SPLIT + p * 256 + tid;
        if (idx < NMASKED) {
            const unsigned m    = g_meta.m[idx];
            const int      cell = m & 4095u;
            const int      i    = cell >> 6;
            const int      j    = cell & 63;
            bt[cell] = (Mf[i] + Mf[j]) * 0.5f;
            ct[cell] = fmaxf(Mf[(m >> 12) & 511u], Mf[(m >> 21) & 511u]);
        }
    }
    asm volatile("fence.proxy.async.shared::cta;" ::: "memory");
    __syncthreads();   // half-1 scatter visible to async proxy

    if (tid == 0) {
        asm volatile("cp.async.bulk.global.shared::cta.bulk_group [%0], [%1], %2;"
                     :: "l"(gb + HCELLS), "r"(smem_u32(bt + HCELLS)), "n"(HCELLS * 4) : "memory");
        asm volatile("cp.async.bulk.commit_group;" ::: "memory");
    } else if (tid == 128) {
        asm volatile("cp.async.bulk.global.shared::cta.bulk_group [%0], [%1], %2;"
                     :: "l"(gc + HCELLS), "r"(smem_u32(ct + HCELLS)), "n"(HCELLS * 4) : "memory");
        asm volatile("cp.async.bulk.commit_group;" ::: "memory");
    }

    // 16 CTAs (d == 0) emit the broadcast mask slice for their batch b.
    if ((bd & (ND - 1)) == 0) {
        float* mp = mask_out + (size_t)(bd >> 9) * NCELLS;
        #pragma unroll
        for (int p = 0; p < 4; p++) {
            const int c0 = (p * 256 + tid) * 4;
            *reinterpret_cast<float4*>(mp + c0) =
                *reinterpret_cast<const float4*>(&g_mask.m[c0]);
        }
    }

    // Issuing threads drain their groups before CTA teardown (smem safety).
    if (tid == 0 || tid == 128)
        asm volatile("cp.async.bulk.wait_group 0;" ::: "memory");
}

extern "C" void kernel_launch(void* const* d_in, const int* in_sizes, int n_in,
                              void* d_out, int out_size) {
    const float* x = (const float*)d_in[0];
    float* out = (float*)d_out;

    const size_t map_elems = (size_t)NB * ND * NN * NN;   // 33,554,432
    float* boundary = out;
    float* content  = out + map_elems;
    float* mask_out = out + 2 * map_elems;

    sbc_kernel<<<NB * ND, 256>>>(x, boundary, content, mask_out);
}

// round 16
// speedup vs baseline: 1.0286x; 1.0286x over previous
#include <cuda_runtime.h>
#include <cuda_bf16.h>
#include <cstdint>

// SparseBoundaryContent: x [16, 512, 64] f32.
// boundary(i,j) = (x[i]+x[j])/2 on masked cells, content(i,j) = max(x[i..j])
// on masked cells, 0 elsewhere.
// Output layout (flat f32): [boundary B*D*N*N][content B*D*N*N][mask B*N*N].
//
// FINAL (R13 champion): 1 row/CTA, grid 8192, 256 threads. Warp-0 sparse-max
// table build (syncwarp-only) overlapped with the other warps' zero-fill;
// scatter only the 1104 masked cells; two 16KB cp.async.bulk stores issued by
// separate threads. 2 block barriers per CTA.
//
// The kernel runs at the chip-wide LTS store-accept cap (~6300 B/cyc,
// path-independent): 268.7 MB / 42.2us ncu = 6.36 TB/s. Output bytes are
// irreducible, so this is the hardware floor; verified by 6 structurally
// distinct designs all converging to 42-45us.

#define NB 16
#define ND 512
#define NN 64
#define NCELLS 4096          // 64*64 cells per (b,d) row
#define NMASKED 1104         // masked cells per tile (incl. diagonal)

constexpr bool cell_mask_ct(int i, int j) {
    int d = j - i;
    if (d < 0)  return false;
    if (d <= 15) return true;                              // stride-1 offsets 0..15
    if (d <= 31) return (d & 1) && !(i & 1);               // stride-2: odd 17..31, i even
    return (d >= 35) && ((d & 3) == 3) && !(i & 3);        // stride-4: 35,39,..,63, i%4==0
}

struct MaskTab { float m[NCELLS]; };
constexpr MaskTab gen_mask() {
    MaskTab t{};
    for (int i = 0; i < NN; i++)
        for (int j = 0; j < NN; j++)
            t.m[i * NN + j] = cell_mask_ct(i, j) ? 1.0f : 0.0f;
    return t;
}
__device__ constexpr MaskTab g_mask = gen_mask();

struct Meta { unsigned int m[NMASKED]; };
constexpr Meta gen_meta() {
    Meta t{};
    int cnt = 0;
    for (int i = 0; i < NN; i++) {
        for (int j = 0; j < NN; j++) {
            if (!cell_mask_ct(i, j)) continue;
            int len = j - i + 1;
            int k = 0;
            while ((1 << (k + 1)) <= len) k++;             // floor(log2(len))
            int ri = j + 1 - (1 << k);
            unsigned offL = (unsigned)(k * NN + i);
            unsigned offR = (unsigned)(k * NN + ri);
            t.m[cnt++] = (unsigned)(i * NN + j) | (offL << 12) | (offR << 21);
        }
    }
    return t;
}
__device__ constexpr Meta g_meta = gen_meta();

__device__ __forceinline__ uint32_t smem_u32(const void* p) {
    uint32_t a;
    asm("{ .reg .u64 t; cvta.to.shared.u64 t, %1; cvt.u32.u64 %0, t; }"
        : "=r"(a) : "l"(p));
    return a;
}

__global__ void __launch_bounds__(256)
sbc_kernel(const float* __restrict__ x,
           float* __restrict__ boundary,
           float* __restrict__ content,
           float* __restrict__ mask_out)
{
    __shared__ float Mf[7 * NN];                 // sparse max table
    __shared__ alignas(128) float bt[NCELLS];    // boundary tile (16 KB)
    __shared__ alignas(128) float ct[NCELLS];    // content tile  (16 KB)

    const int bd  = blockIdx.x;                  // bd = b*ND + d
    const int tid = threadIdx.x;
    const int wid = tid >> 5;
    const int lid = tid & 31;

    // Warp 0: early x load + sparse-max table build (syncwarp only), with its
    // zero-fill share issued between the LDG and its first use (latency hide).
    // Warps 1..7: zero-fill the two 16 KB tiles.
    if (wid == 0) {
        const float* xr = x + (size_t)bd * NN;
        const float x0 = xr[lid];
        const float x1 = xr[lid + 32];
        const float4 z = make_float4(0.f, 0.f, 0.f, 0.f);
        #pragma unroll
        for (int p = 0; p < 4; p++) {
            reinterpret_cast<float4*>(bt)[p * 256 + tid] = z;
            reinterpret_cast<float4*>(ct)[p * 256 + tid] = z;
        }
        Mf[lid]      = x0;
        Mf[lid + 32] = x1;
        __syncwarp();
        #pragma unroll
        for (int k = 1; k < 7; k++) {
            const int h  = 1 << (k - 1);
            const int e1 = lid + 32;
            int o0 = lid + h; if (o0 > 63) o0 = 63;
            int o1 = e1  + h; if (o1 > 63) o1 = 63;
            const float a = fmaxf(Mf[(k - 1) * NN + lid], Mf[(k - 1) * NN + o0]);
            const float b = fmaxf(Mf[(k - 1) * NN + e1],  Mf[(k - 1) * NN + o1]);
            Mf[k * NN + lid] = a;
            Mf[k * NN + e1]  = b;
            __syncwarp();
        }
    } else {
        const float4 z = make_float4(0.f, 0.f, 0.f, 0.f);
        #pragma unroll
        for (int p = 0; p < 4; p++) {
            reinterpret_cast<float4*>(bt)[p * 256 + tid] = z;
            reinterpret_cast<float4*>(ct)[p * 256 + tid] = z;
        }
    }
    __syncthreads();   // Mf ready, tiles zeroed

    // Scatter boundary + content at the 1104 masked cells (<=5 per thread).
    #pragma unroll
    for (int p = 0; p < 5; p++) {
        const int idx = p * 256 + tid;
        if (idx < NMASKED) {
            const unsigned m    = g_meta.m[idx];
            const int      cell = m & 4095u;
            const int      i    = cell >> 6;
            const int      j    = cell & 63;
            bt[cell] = (Mf[i] + Mf[j]) * 0.5f;
            ct[cell] = fmaxf(Mf[(m >> 12) & 511u], Mf[(m >> 21) & 511u]);
        }
    }

    asm volatile("fence.proxy.async.shared::cta;" ::: "memory");
    __syncthreads();   // scatter + zero-fill visible to async proxy

    // Dual-thread bulk-store issue: two independent bulk groups.
    if (tid == 0) {
        float* gb = boundary + (size_t)bd * NCELLS;
        asm volatile("cp.async.bulk.global.shared::cta.bulk_group [%0], [%1], %2;"
                     :: "l"(gb), "r"(smem_u32(bt)), "n"(NCELLS * 4) : "memory");
        asm volatile("cp.async.bulk.commit_group;" ::: "memory");
    } else if (tid == 128) {
        float* gc = content + (size_t)bd * NCELLS;
        asm volatile("cp.async.bulk.global.shared::cta.bulk_group [%0], [%1], %2;"
                     :: "l"(gc), "r"(smem_u32(ct)), "n"(NCELLS * 4) : "memory");
        asm volatile("cp.async.bulk.commit_group;" ::: "memory");
    }

    // 16 CTAs (d == 0) emit the broadcast mask slice for their batch b.
    if ((bd & (ND - 1)) == 0) {
        float* mp = mask_out + (size_t)(bd >> 9) * NCELLS;
        #pragma unroll
        for (int p = 0; p < 4; p++) {
            const int c0 = (p * 256 + tid) * 4;
            *reinterpret_cast<float4*>(mp + c0) =
                *reinterpret_cast<const float4*>(&g_mask.m[c0]);
        }
    }

    // Each issuing thread drains its own group before CTA teardown.
    if (tid == 0 || tid == 128)
        asm volatile("cp.async.bulk.wait_group 0;" ::: "memory");
}

extern "C" void kernel_launch(void* const* d_in, const int* in_sizes, int n_in,
                              void* d_out, int out_size) {
    const float* x = (const float*)d_in[0];
    float* out = (float*)d_out;

    const size_t map_elems = (size_t)NB * ND * NN * NN;   // 33,554,432
    float* boundary = out;
    float* content  = out + map_elems;
    float* mask_out = out + 2 * map_elems;

    sbc_kernel<<<NB * ND, 256>>>(x, boundary, content, mask_out);
}

// round 17
// speedup vs baseline: 1.0301x; 1.0014x over previous
#include <cuda_runtime.h>
#include <cuda_bf16.h>
#include <cstdint>

// SparseBoundaryContent: x [16, 512, 64] f32.
// boundary(i,j) = (x[i]+x[j])/2 on masked cells, content(i,j) = max(x[i..j])
// on masked cells, 0 elsewhere.
// Output layout (flat f32): [boundary B*D*N*N][content B*D*N*N][mask B*N*N].
//
// R16 (champion + critical-warp shave): warp 0 does ONLY x-load + sparse-max
// build (its zero-fill share moved to warps 1-7, whose path is far shorter
// and fully overlapped). Otherwise identical to the R13/R15 champion:
// 1 row/CTA, grid 8192, 256 threads, scatter 1104 masked cells, two 16KB
// cp.async.bulk stores, 2 block barriers per CTA.
//
// Kernel runs at the memory-system store wall (~6.3 TB/s effective): six
// structurally distinct designs all converge to 42-44us ncu.

#define NB 16
#define ND 512
#define NN 64
#define NCELLS 4096          // 64*64 cells per (b,d) row
#define NMASKED 1104         // masked cells per tile (incl. diagonal)

constexpr bool cell_mask_ct(int i, int j) {
    int d = j - i;
    if (d < 0)  return false;
    if (d <= 15) return true;                              // stride-1 offsets 0..15
    if (d <= 31) return (d & 1) && !(i & 1);               // stride-2: odd 17..31, i even
    return (d >= 35) && ((d & 3) == 3) && !(i & 3);        // stride-4: 35,39,..,63, i%4==0
}

struct MaskTab { float m[NCELLS]; };
constexpr MaskTab gen_mask() {
    MaskTab t{};
    for (int i = 0; i < NN; i++)
        for (int j = 0; j < NN; j++)
            t.m[i * NN + j] = cell_mask_ct(i, j) ? 1.0f : 0.0f;
    return t;
}
__device__ constexpr MaskTab g_mask = gen_mask();

struct Meta { unsigned int m[NMASKED]; };
constexpr Meta gen_meta() {
    Meta t{};
    int cnt = 0;
    for (int i = 0; i < NN; i++) {
        for (int j = 0; j < NN; j++) {
            if (!cell_mask_ct(i, j)) continue;
            int len = j - i + 1;
            int k = 0;
            while ((1 << (k + 1)) <= len) k++;             // floor(log2(len))
            int ri = j + 1 - (1 << k);
            unsigned offL = (unsigned)(k * NN + i);
            unsigned offR = (unsigned)(k * NN + ri);
            t.m[cnt++] = (unsigned)(i * NN + j) | (offL << 12) | (offR << 21);
        }
    }
    return t;
}
__device__ constexpr Meta g_meta = gen_meta();

__device__ __forceinline__ uint32_t smem_u32(const void* p) {
    uint32_t a;
    asm("{ .reg .u64 t; cvta.to.shared.u64 t, %1; cvt.u32.u64 %0, t; }"
        : "=r"(a) : "l"(p));
    return a;
}

__global__ void __launch_bounds__(256)
sbc_kernel(const float* __restrict__ x,
           float* __restrict__ boundary,
           float* __restrict__ content,
           float* __restrict__ mask_out)
{
    __shared__ float Mf[7 * NN];                 // sparse max table
    __shared__ alignas(128) float bt[NCELLS];    // boundary tile (16 KB)
    __shared__ alignas(128) float ct[NCELLS];    // content tile  (16 KB)

    const int bd  = blockIdx.x;                  // bd = b*ND + d
    const int tid = threadIdx.x;
    const int wid = tid >> 5;
    const int lid = tid & 31;

    if (wid == 0) {
        // Critical path only: x load -> Mf -> 6-level sparse-max build.
        const float* xr = x + (size_t)bd * NN;
        Mf[lid]      = xr[lid];
        Mf[lid + 32] = xr[lid + 32];
        __syncwarp();
        #pragma unroll
        for (int k = 1; k < 7; k++) {
            const int h  = 1 << (k - 1);
            const int e1 = lid + 32;
            int o0 = lid + h; if (o0 > 63) o0 = 63;
            int o1 = e1  + h; if (o1 > 63) o1 = 63;
            const float a = fmaxf(Mf[(k - 1) * NN + lid], Mf[(k - 1) * NN + o0]);
            const float b = fmaxf(Mf[(k - 1) * NN + e1],  Mf[(k - 1) * NN + o1]);
            Mf[k * NN + lid] = a;
            Mf[k * NN + e1]  = b;
            __syncwarp();
        }
    } else {
        // Warps 1..7 (224 threads) zero-fill both 16 KB tiles entirely.
        const int t = tid - 32;                  // 0..223
        const float4 z = make_float4(0.f, 0.f, 0.f, 0.f);
        #pragma unroll
        for (int p = 0; p < 5; p++) {
            const int idx = p * 224 + t;         // float4 index, 0..1119
            if (idx < NCELLS / 4) {
                reinterpret_cast<float4*>(bt)[idx] = z;
                reinterpret_cast<float4*>(ct)[idx] = z;
            }
        }
    }
    __syncthreads();   // Mf ready, tiles zeroed

    // Scatter boundary + content at the 1104 masked cells (<=5 per thread).
    #pragma unroll
    for (int p = 0; p < 5; p++) {
        const int idx = p * 256 + tid;
        if (idx < NMASKED) {
            const unsigned m    = g_meta.m[idx];
            const int      cell = m & 4095u;
            const int      i    = cell >> 6;
            const int      j    = cell & 63;
            bt[cell] = (Mf[i] + Mf[j]) * 0.5f;
            ct[cell] = fmaxf(Mf[(m >> 12) & 511u], Mf[(m >> 21) & 511u]);
        }
    }

    asm volatile("fence.proxy.async.shared::cta;" ::: "memory");
    __syncthreads();   // scatter + zero-fill visible to async proxy

    // Dual-thread bulk-store issue: two independent bulk groups.
    if (tid == 0) {
        float* gb = boundary + (size_t)bd * NCELLS;
        asm volatile("cp.async.bulk.global.shared::cta.bulk_group [%0], [%1], %2;"
                     :: "l"(gb), "r"(smem_u32(bt)), "n"(NCELLS * 4) : "memory");
        asm volatile("cp.async.bulk.commit_group;" ::: "memory");
    } else if (tid == 128) {
        float* gc = content + (size_t)bd * NCELLS;
        asm volatile("cp.async.bulk.global.shared::cta.bulk_group [%0], [%1], %2;"
                     :: "l"(gc), "r"(smem_u32(ct)), "n"(NCELLS * 4) : "memory");
        asm volatile("cp.async.bulk.commit_group;" ::: "memory");
    }

    // 16 CTAs (d == 0) emit the broadcast mask slice for their batch b.
    if ((bd & (ND - 1)) == 0) {
        float* mp = mask_out + (size_t)(bd >> 9) * NCELLS;
        #pragma unroll
        for (int p = 0; p < 4; p++) {
            const int c0 = (p * 256 + tid) * 4;
            *reinterpret_cast<float4*>(mp + c0) =
                *reinterpret_cast<const float4*>(&g_mask.m[c0]);
        }
    }

    // Each issuing thread drains its own group before CTA teardown.
    if (tid == 0 || tid == 128)
        asm volatile("cp.async.bulk.wait_group 0;" ::: "memory");
}

extern "C" void kernel_launch(void* const* d_in, const int* in_sizes, int n_in,
                              void* d_out, int out_size) {
    const float* x = (const float*)d_in[0];
    float* out = (float*)d_out;

    const size_t map_elems = (size_t)NB * ND * NN * NN;   // 33,554,432
    float* boundary = out;
    float* content  = out + map_elems;
    float* mask_out = out + 2 * map_elems;

    sbc_kernel<<<NB * ND, 256>>>(x, boundary, content, mask_out);
}